// round 5
// baseline (speedup 1.0000x reference)
#include <cuda_runtime.h>
#include <cuda_fp16.h>

#define D 64
#define NODES_CAP 50000
#define EDGES_CAP 1600000
#define SCAN_BLK 1024

// ---------------- scratch (static device globals; no allocation) ----------------
__device__ int   g_counts[NODES_CAP];
__device__ int   g_roff[NODES_CAP];      // partial prefix; after fill: +bsum = final roff[n+1]
__device__ int   g_bsum[64];
__device__ int   g_scan_done;
__device__ float g_wsum[NODES_CAP];
__device__ int2  g_edge[EDGES_CAP];                       // (src, float_as_int(w))
__device__ float g_agg[NODES_CAP * D];                    // fp32 aggregation result
__device__ __align__(128) __half2 g_xh[NODES_CAP * 32];   // fp16 feature rows for gather

// ---------------- zero counters ----------------
__global__ void k_zero(int n_nodes) {
    int i = blockIdx.x * blockDim.x + threadIdx.x;
    if (i < n_nodes) g_counts[i] = 0;
    if (i == 0) g_scan_done = 0;
}

// ---------------- fused init (fp16 convert + hidden=x*t0) + degree histogram ----------------
__global__ void k_initcnt(const float* __restrict__ x, const float* __restrict__ temp,
                          const int* __restrict__ dst,
                          float* __restrict__ hidden, int nd2, int E) {
    int i = blockIdx.x * blockDim.x + threadIdx.x;
    if (i < nd2) {
        float t0 = __ldg(&temp[0]);
        float2 v = ((const float2*)x)[i];
        g_xh[i] = __floats2half2_rn(v.x, v.y);
        ((float2*)hidden)[i] = make_float2(v.x * t0, v.y * t0);
    }
    int e4 = i * 4;
    if (e4 + 4 <= E) {
        int4 d4 = __ldg((const int4*)&dst[e4]);
        atomicAdd(&g_counts[d4.x], 1);
        atomicAdd(&g_counts[d4.y], 1);
        atomicAdd(&g_counts[d4.z], 1);
        atomicAdd(&g_counts[d4.w], 1);
    } else {
        for (int e = e4; e < E; e++) atomicAdd(&g_counts[__ldg(&dst[e])], 1);
    }
}

// ---------------- scan1 + folded block-sum scan (last-block pattern) ----------------
__global__ void k_scan1(int N, int nb) {
    __shared__ int s[SCAN_BLK];
    __shared__ int is_last;
    int tid = threadIdx.x;
    int i = blockIdx.x * SCAN_BLK + tid;
    int v = (i < N) ? g_counts[i] : 0;
    s[tid] = v;
    __syncthreads();
    for (int off = 1; off < SCAN_BLK; off <<= 1) {
        int t = (tid >= off) ? s[tid - off] : 0;
        __syncthreads();
        s[tid] += t;
        __syncthreads();
    }
    if (i < N) g_roff[i] = s[tid] - v;          // block-local exclusive prefix
    if (tid == SCAN_BLK - 1) g_bsum[blockIdx.x] = s[tid];
    __threadfence();
    if (tid == 0) is_last = (atomicAdd(&g_scan_done, 1) == nb - 1);
    __syncthreads();
    if (is_last && tid < 32) {
        int lane = tid;
        int v0 = (lane < nb) ? g_bsum[lane] : 0;
        int v1 = (lane + 32 < nb) ? g_bsum[lane + 32] : 0;
        int s0 = v0;
        #pragma unroll
        for (int off = 1; off < 32; off <<= 1) {
            int t = __shfl_up_sync(0xffffffffu, s0, off);
            if (lane >= off) s0 += t;
        }
        int tot0 = __shfl_sync(0xffffffffu, s0, 31);
        int s1 = v1;
        #pragma unroll
        for (int off = 1; off < 32; off <<= 1) {
            int t = __shfl_up_sync(0xffffffffu, s1, off);
            if (lane >= off) s1 += t;
        }
        if (lane < nb) g_bsum[lane] = s0 - v0;                  // exclusive
        if (lane + 32 < nb) g_bsum[lane + 32] = tot0 + s1 - v1;
    }
}

// ---------------- CSR fill: bump partial roff directly, add block offset at use ----------------
// After this kernel: g_roff[n] + g_bsum[n>>10] == final_roff[n+1]
__global__ void k_fill(const int* __restrict__ src, const int* __restrict__ dst,
                       const float* __restrict__ w, int E) {
    int i = blockIdx.x * blockDim.x + threadIdx.x;
    int e4 = i * 4;
    if (e4 + 4 <= E) {
        int4   s4 = __ldg((const int4*)&src[e4]);
        int4   d4 = __ldg((const int4*)&dst[e4]);
        float4 w4 = __ldg((const float4*)&w[e4]);
        int p0 = atomicAdd(&g_roff[d4.x], 1) + g_bsum[d4.x >> 10];
        int p1 = atomicAdd(&g_roff[d4.y], 1) + g_bsum[d4.y >> 10];
        int p2 = atomicAdd(&g_roff[d4.z], 1) + g_bsum[d4.z >> 10];
        int p3 = atomicAdd(&g_roff[d4.w], 1) + g_bsum[d4.w >> 10];
        g_edge[p0] = make_int2(s4.x, __float_as_int(w4.x));
        g_edge[p1] = make_int2(s4.y, __float_as_int(w4.y));
        g_edge[p2] = make_int2(s4.z, __float_as_int(w4.z));
        g_edge[p3] = make_int2(s4.w, __float_as_int(w4.w));
    } else {
        for (int e = e4; e < E; e++) {
            int d = __ldg(&dst[e]);
            int p = atomicAdd(&g_roff[d], 1) + g_bsum[d >> 10];
            g_edge[p] = make_int2(__ldg(&src[e]), __float_as_int(__ldg(&w[e])));
        }
    }
}

// ---------------- SpMM: one warp per dst node, fp16 gather, fp32 accumulate ----------------
// agg[n] = sum over in-edges e of x[src_e] * w_e ; layer 0 also stores wsum[n] = sum w_e
__global__ void k_spmm(int N, int store_wsum) {
    int warp = (blockIdx.x * blockDim.x + threadIdx.x) >> 5;
    int lane = threadIdx.x & 31;
    if (warp >= N) return;
    int beg = (warp == 0) ? 0 : (__ldg(&g_roff[warp - 1]) + g_bsum[(warp - 1) >> 10]);
    int end = __ldg(&g_roff[warp]) + g_bsum[warp >> 10];
    float2 acc = make_float2(0.f, 0.f);
    float ws = 0.f;
    int e = beg;
    for (; e + 8 <= end; e += 8) {
        int2 ed[8];
        __half2 v[8];
        #pragma unroll
        for (int j = 0; j < 8; j++) ed[j] = __ldg(&g_edge[e + j]);
        #pragma unroll
        for (int j = 0; j < 8; j++) v[j] = __ldg(&g_xh[ed[j].x * 32 + lane]);
        #pragma unroll
        for (int j = 0; j < 8; j++) {
            float wt = __int_as_float(ed[j].y);
            ws += wt;
            float2 f = __half22float2(v[j]);
            acc.x = fmaf(f.x, wt, acc.x);
            acc.y = fmaf(f.y, wt, acc.y);
        }
    }
    for (; e < end; e++) {
        int2 ee = __ldg(&g_edge[e]);
        float wt = __int_as_float(ee.y);
        ws += wt;
        float2 f = __half22float2(__ldg(&g_xh[ee.x * 32 + lane]));
        acc.x = fmaf(f.x, wt, acc.x);
        acc.y = fmaf(f.y, wt, acc.y);
    }
    ((float2*)g_agg)[warp * 32 + lane] = acc;
    if (store_wsum && lane == 0) g_wsum[warp] = ws;
}

// ---------------- fused GEMM + bias*wsum + relu + hidden accumulation ----------------
// xn[n,o] = relu( sum_d agg[n,d]*W[o,d] + b[o]*wsum[n] )  -> stored fp16 in g_xh
// hidden[n,o] += xn[n,o] * temp[li+1]
__global__ void k_gemm(const float* __restrict__ Wl, const float* __restrict__ bl,
                       const float* __restrict__ temp, int li,
                       float* __restrict__ hidden, int N) {
    __shared__ __align__(16) float As[64][68];   // As[d][n]
    __shared__ __align__(16) float Bs[64][68];   // Bs[d][o]
    int tid = threadIdx.x;
    int bn = blockIdx.x * 64;
    float t = __ldg(&temp[li + 1]);

    for (int idx = tid; idx < 4096; idx += 256) {
        int o = idx >> 6, d = idx & 63;
        Bs[d][o] = __ldg(&Wl[o * 64 + d]);
    }
    for (int idx = tid; idx < 4096; idx += 256) {
        int n = idx >> 6, d = idx & 63;
        int node = bn + n;
        As[d][n] = (node < N) ? g_agg[node * 64 + d] : 0.f;
    }
    __syncthreads();

    int tx = tid & 15;          // output-column tile
    int ty = tid >> 4;          // node tile
    int o0 = tx * 4, n0 = ty * 4;

    float acc[4][4] = {};
    #pragma unroll
    for (int k = 0; k < 64; k++) {
        float4 a = *(const float4*)&As[k][n0];
        float4 b = *(const float4*)&Bs[k][o0];
        acc[0][0] = fmaf(a.x, b.x, acc[0][0]); acc[0][1] = fmaf(a.x, b.y, acc[0][1]);
        acc[0][2] = fmaf(a.x, b.z, acc[0][2]); acc[0][3] = fmaf(a.x, b.w, acc[0][3]);
        acc[1][0] = fmaf(a.y, b.x, acc[1][0]); acc[1][1] = fmaf(a.y, b.y, acc[1][1]);
        acc[1][2] = fmaf(a.y, b.z, acc[1][2]); acc[1][3] = fmaf(a.y, b.w, acc[1][3]);
        acc[2][0] = fmaf(a.z, b.x, acc[2][0]); acc[2][1] = fmaf(a.z, b.y, acc[2][1]);
        acc[2][2] = fmaf(a.z, b.z, acc[2][2]); acc[2][3] = fmaf(a.z, b.w, acc[2][3]);
        acc[3][0] = fmaf(a.w, b.x, acc[3][0]); acc[3][1] = fmaf(a.w, b.y, acc[3][1]);
        acc[3][2] = fmaf(a.w, b.z, acc[3][2]); acc[3][3] = fmaf(a.w, b.w, acc[3][3]);
    }

    float4 bo = *(const float4*)&bl[o0];
    #pragma unroll
    for (int i = 0; i < 4; i++) {
        int node = bn + n0 + i;
        if (node >= N) continue;
        float ws = g_wsum[node];
        float4 r;
        r.x = fmaxf(fmaf(bo.x, ws, acc[i][0]), 0.f);
        r.y = fmaxf(fmaf(bo.y, ws, acc[i][1]), 0.f);
        r.z = fmaxf(fmaf(bo.z, ws, acc[i][2]), 0.f);
        r.w = fmaxf(fmaf(bo.w, ws, acc[i][3]), 0.f);
        g_xh[node * 32 + (o0 >> 1) + 0] = __floats2half2_rn(r.x, r.y);
        g_xh[node * 32 + (o0 >> 1) + 1] = __floats2half2_rn(r.z, r.w);
        float4 h = *(float4*)&hidden[node * 64 + o0];
        h.x = fmaf(r.x, t, h.x);
        h.y = fmaf(r.y, t, h.y);
        h.z = fmaf(r.z, t, h.z);
        h.w = fmaf(r.w, t, h.w);
        *(float4*)&hidden[node * 64 + o0] = h;
    }
}

extern "C" void kernel_launch(void* const* d_in, const int* in_sizes, int n_in,
                              void* d_out, int out_size) {
    const float* x    = (const float*)d_in[0];
    const float* w    = (const float*)d_in[1];
    const float* W    = (const float*)d_in[2];
    const float* b    = (const float*)d_in[3];
    const float* temp = (const float*)d_in[4];
    const int*   src  = (const int*)d_in[5];
    const int*   dst  = (const int*)d_in[6];
    float* hidden = (float*)d_out;

    int nd = in_sizes[0];          // N * D
    int N  = nd / D;
    int E  = in_sizes[1];
    int L  = in_sizes[3] / D;
    int nd2 = nd / 2;

    k_zero<<<(N + 255) / 256, 256>>>(N);
    int e4 = (E + 3) / 4;
    int mx = (e4 > nd2) ? e4 : nd2;
    k_initcnt<<<(mx + 255) / 256, 256>>>(x, temp, dst, hidden, nd2, E);
    int nb = (N + SCAN_BLK - 1) / SCAN_BLK;
    k_scan1<<<nb, SCAN_BLK>>>(N, nb);
    k_fill<<<(e4 + 255) / 256, 256>>>(src, dst, w, E);

    int spmm_blocks = (N + 7) / 8;            // 8 warps (nodes) per 256-thread block
    int gemm_blocks = (N + 63) / 64;
    for (int i = 0; i < L; i++) {
        k_spmm<<<spmm_blocks, 256>>>(N, (i == 0) ? 1 : 0);
        k_gemm<<<gemm_blocks, 256>>>(W + i * D * D, b + i * D, temp, i, hidden, N);
    }
}

// round 6
// speedup vs baseline: 1.1480x; 1.1480x over previous
#include <cuda_runtime.h>
#include <cuda_fp16.h>
#include <cstdint>

#define D 64
#define NODES_CAP 50000
#define EDGES_CAP 1600000
#define SCAN_BLK 1024

// ---------------- scratch (static device globals; no allocation) ----------------
__device__ int   g_counts[NODES_CAP];
__device__ int   g_roff[NODES_CAP];      // partial prefix; after fill: +bsum = final roff[n+1]
__device__ int   g_bsum[64];
__device__ int   g_scan_done;
__device__ float g_wsum[NODES_CAP];
__device__ int2  g_edge[EDGES_CAP];                       // (src, float_as_int(w))
__device__ float g_agg[NODES_CAP * D];                    // fp32 aggregation result
__device__ __align__(128) __half2 g_xh[NODES_CAP * 32];   // fp16 feature rows for gather

// ---------------- zero counters ----------------
__global__ void k_zero(int n_nodes) {
    int i = blockIdx.x * blockDim.x + threadIdx.x;
    if (i < n_nodes) g_counts[i] = 0;
    if (i == 0) g_scan_done = 0;
}

// ---------------- fused init (fp16 convert + hidden=x*t0) + degree histogram ----------------
__global__ void k_initcnt(const float* __restrict__ x, const float* __restrict__ temp,
                          const int* __restrict__ dst,
                          float* __restrict__ hidden, int nd2, int E) {
    int i = blockIdx.x * blockDim.x + threadIdx.x;
    if (i < nd2) {
        float t0 = __ldg(&temp[0]);
        float2 v = ((const float2*)x)[i];
        g_xh[i] = __floats2half2_rn(v.x, v.y);
        ((float2*)hidden)[i] = make_float2(v.x * t0, v.y * t0);
    }
    int e4 = i * 4;
    if (e4 + 4 <= E) {
        int4 d4 = __ldg((const int4*)&dst[e4]);
        atomicAdd(&g_counts[d4.x], 1);
        atomicAdd(&g_counts[d4.y], 1);
        atomicAdd(&g_counts[d4.z], 1);
        atomicAdd(&g_counts[d4.w], 1);
    } else {
        for (int e = e4; e < E; e++) atomicAdd(&g_counts[__ldg(&dst[e])], 1);
    }
}

// ---------------- scan1 + folded block-sum scan (last-block pattern) ----------------
__global__ void k_scan1(int N, int nb) {
    __shared__ int s[SCAN_BLK];
    __shared__ int is_last;
    int tid = threadIdx.x;
    int i = blockIdx.x * SCAN_BLK + tid;
    int v = (i < N) ? g_counts[i] : 0;
    s[tid] = v;
    __syncthreads();
    for (int off = 1; off < SCAN_BLK; off <<= 1) {
        int t = (tid >= off) ? s[tid - off] : 0;
        __syncthreads();
        s[tid] += t;
        __syncthreads();
    }
    if (i < N) g_roff[i] = s[tid] - v;          // block-local exclusive prefix
    if (tid == SCAN_BLK - 1) g_bsum[blockIdx.x] = s[tid];
    __threadfence();
    if (tid == 0) is_last = (atomicAdd(&g_scan_done, 1) == nb - 1);
    __syncthreads();
    if (is_last && tid < 32) {
        int lane = tid;
        int v0 = (lane < nb) ? g_bsum[lane] : 0;
        int v1 = (lane + 32 < nb) ? g_bsum[lane + 32] : 0;
        int s0 = v0;
        #pragma unroll
        for (int off = 1; off < 32; off <<= 1) {
            int t = __shfl_up_sync(0xffffffffu, s0, off);
            if (lane >= off) s0 += t;
        }
        int tot0 = __shfl_sync(0xffffffffu, s0, 31);
        int s1 = v1;
        #pragma unroll
        for (int off = 1; off < 32; off <<= 1) {
            int t = __shfl_up_sync(0xffffffffu, s1, off);
            if (lane >= off) s1 += t;
        }
        if (lane < nb) g_bsum[lane] = s0 - v0;                  // exclusive
        if (lane + 32 < nb) g_bsum[lane + 32] = tot0 + s1 - v1;
    }
}

// ---------------- CSR fill: bump partial roff directly, add block offset at use ----------------
// After this kernel: g_roff[n] + g_bsum[n>>10] == final_roff[n+1]
__global__ void k_fill(const int* __restrict__ src, const int* __restrict__ dst,
                       const float* __restrict__ w, int E) {
    int i = blockIdx.x * blockDim.x + threadIdx.x;
    int e4 = i * 4;
    if (e4 + 4 <= E) {
        int4   s4 = __ldg((const int4*)&src[e4]);
        int4   d4 = __ldg((const int4*)&dst[e4]);
        float4 w4 = __ldg((const float4*)&w[e4]);
        int p0 = atomicAdd(&g_roff[d4.x], 1) + g_bsum[d4.x >> 10];
        int p1 = atomicAdd(&g_roff[d4.y], 1) + g_bsum[d4.y >> 10];
        int p2 = atomicAdd(&g_roff[d4.z], 1) + g_bsum[d4.z >> 10];
        int p3 = atomicAdd(&g_roff[d4.w], 1) + g_bsum[d4.w >> 10];
        g_edge[p0] = make_int2(s4.x, __float_as_int(w4.x));
        g_edge[p1] = make_int2(s4.y, __float_as_int(w4.y));
        g_edge[p2] = make_int2(s4.z, __float_as_int(w4.z));
        g_edge[p3] = make_int2(s4.w, __float_as_int(w4.w));
    } else {
        for (int e = e4; e < E; e++) {
            int d = __ldg(&dst[e]);
            int p = atomicAdd(&g_roff[d], 1) + g_bsum[d >> 10];
            g_edge[p] = make_int2(__ldg(&src[e]), __float_as_int(__ldg(&w[e])));
        }
    }
}

// ---------------- SpMM: one warp per dst node, fp16 gather, fp32 accumulate ----------------
// agg[n] = sum over in-edges e of x[src_e] * w_e ; layer 0 also stores wsum[n] = sum w_e
template <int STORE_WSUM>
__global__ void k_spmm(int N) {
    int warp = (blockIdx.x * blockDim.x + threadIdx.x) >> 5;
    int lane = threadIdx.x & 31;
    if (warp >= N) return;
    int beg = (warp == 0) ? 0 : (__ldg(&g_roff[warp - 1]) + g_bsum[(warp - 1) >> 10]);
    int end = __ldg(&g_roff[warp]) + g_bsum[warp >> 10];
    float2 acc = make_float2(0.f, 0.f);
    float ws = 0.f;
    int e = beg;
    for (; e + 8 <= end; e += 8) {
        int2 ed[8];
        __half2 v[8];
        #pragma unroll
        for (int j = 0; j < 8; j++) ed[j] = __ldg(&g_edge[e + j]);
        #pragma unroll
        for (int j = 0; j < 8; j++) v[j] = __ldg(&g_xh[ed[j].x * 32 + lane]);
        #pragma unroll
        for (int j = 0; j < 8; j++) {
            float wt = __int_as_float(ed[j].y);
            if (STORE_WSUM) ws += wt;
            float2 f = __half22float2(v[j]);
            acc.x = fmaf(f.x, wt, acc.x);
            acc.y = fmaf(f.y, wt, acc.y);
        }
    }
    for (; e < end; e++) {
        int2 ee = __ldg(&g_edge[e]);
        float wt = __int_as_float(ee.y);
        if (STORE_WSUM) ws += wt;
        float2 f = __half22float2(__ldg(&g_xh[ee.x * 32 + lane]));
        acc.x = fmaf(f.x, wt, acc.x);
        acc.y = fmaf(f.y, wt, acc.y);
    }
    ((float2*)g_agg)[warp * 32 + lane] = acc;
    if (STORE_WSUM && lane == 0) g_wsum[warp] = ws;
}

// ---------------- tf32 tensor-core GEMM + bias*wsum + relu + hidden accumulation ----------------
// xn[n,o] = relu( sum_d agg[n,d]*W[o,d] + b[o]*wsum[n] )  -> stored fp16 in g_xh
// hidden[n,o] += xn[n,o] * temp[li+1]
// Tile: 64 nodes x 64 outputs, K=64. 8 warps: warpM = wid&3 (16 rows), warpN = wid>>2 (32 cols).
__device__ __forceinline__ uint32_t f2tf32(float f) {
    uint32_t r;
    asm("cvt.rna.tf32.f32 %0, %1;" : "=r"(r) : "f"(f));
    return r;
}

__global__ void k_gemm(const float* __restrict__ Wl, const float* __restrict__ bl,
                       const float* __restrict__ temp, int li,
                       float* __restrict__ hidden, int N) {
    __shared__ uint32_t As[64][68];   // As[node][d], tf32 bits; stride 68 -> bank = 4*row+col
    __shared__ uint32_t Ws[64][68];   // Ws[o][d], tf32 bits
    int tid = threadIdx.x;
    int bn = blockIdx.x * 64;
    float t = __ldg(&temp[li + 1]);

    for (int idx = tid; idx < 4096; idx += 256) {
        int o = idx >> 6, d = idx & 63;
        Ws[o][d] = f2tf32(__ldg(&Wl[idx]));          // idx == o*64+d
    }
    for (int idx = tid; idx < 4096; idx += 256) {
        int n = idx >> 6, d = idx & 63;
        int node = bn + n;
        float v = (node < N) ? g_agg[node * 64 + d] : 0.f;
        As[n][d] = f2tf32(v);
    }
    __syncthreads();

    int wid = tid >> 5, lane = tid & 31;
    int g = lane >> 2, tg = lane & 3;
    int m0 = (wid & 3) * 16;
    int n0 = (wid >> 2) * 32;

    float acc[4][4] = {};   // acc[j] = n8-tile j of this warp's m16n32
    #pragma unroll
    for (int k0 = 0; k0 < 64; k0 += 8) {
        uint32_t a0 = As[m0 + g][k0 + tg];
        uint32_t a1 = As[m0 + g + 8][k0 + tg];
        uint32_t a2 = As[m0 + g][k0 + tg + 4];
        uint32_t a3 = As[m0 + g + 8][k0 + tg + 4];
        #pragma unroll
        for (int j = 0; j < 4; j++) {
            uint32_t b0 = Ws[n0 + j * 8 + g][k0 + tg];
            uint32_t b1 = Ws[n0 + j * 8 + g][k0 + tg + 4];
            asm volatile(
                "mma.sync.aligned.m16n8k8.row.col.f32.tf32.tf32.f32 "
                "{%0,%1,%2,%3}, {%4,%5,%6,%7}, {%8,%9}, {%0,%1,%2,%3};"
                : "+f"(acc[j][0]), "+f"(acc[j][1]), "+f"(acc[j][2]), "+f"(acc[j][3])
                : "r"(a0), "r"(a1), "r"(a2), "r"(a3), "r"(b0), "r"(b1));
        }
    }

    // epilogue: thread holds rows (m0+g, m0+g+8), cols (2tg, 2tg+1) per n8-tile
    int node0 = bn + m0 + g;
    int node1 = node0 + 8;
    float ws0 = (node0 < N) ? g_wsum[node0] : 0.f;
    float ws1 = (node1 < N) ? g_wsum[node1] : 0.f;
    #pragma unroll
    for (int j = 0; j < 4; j++) {
        int o = n0 + j * 8 + 2 * tg;
        float b0 = __ldg(&bl[o]), b1 = __ldg(&bl[o + 1]);
        if (node0 < N) {
            float r0 = fmaxf(fmaf(b0, ws0, acc[j][0]), 0.f);
            float r1 = fmaxf(fmaf(b1, ws0, acc[j][1]), 0.f);
            g_xh[node0 * 32 + (o >> 1)] = __floats2half2_rn(r0, r1);
            float2 h = *(float2*)&hidden[node0 * 64 + o];
            h.x = fmaf(r0, t, h.x);
            h.y = fmaf(r1, t, h.y);
            *(float2*)&hidden[node0 * 64 + o] = h;
        }
        if (node1 < N) {
            float r2 = fmaxf(fmaf(b0, ws1, acc[j][2]), 0.f);
            float r3 = fmaxf(fmaf(b1, ws1, acc[j][3]), 0.f);
            g_xh[node1 * 32 + (o >> 1)] = __floats2half2_rn(r2, r3);
            float2 h = *(float2*)&hidden[node1 * 64 + o];
            h.x = fmaf(r2, t, h.x);
            h.y = fmaf(r3, t, h.y);
            *(float2*)&hidden[node1 * 64 + o] = h;
        }
    }
}

extern "C" void kernel_launch(void* const* d_in, const int* in_sizes, int n_in,
                              void* d_out, int out_size) {
    const float* x    = (const float*)d_in[0];
    const float* w    = (const float*)d_in[1];
    const float* W    = (const float*)d_in[2];
    const float* b    = (const float*)d_in[3];
    const float* temp = (const float*)d_in[4];
    const int*   src  = (const int*)d_in[5];
    const int*   dst  = (const int*)d_in[6];
    float* hidden = (float*)d_out;

    int nd = in_sizes[0];          // N * D
    int N  = nd / D;
    int E  = in_sizes[1];
    int L  = in_sizes[3] / D;
    int nd2 = nd / 2;

    k_zero<<<(N + 255) / 256, 256>>>(N);
    int e4 = (E + 3) / 4;
    int mx = (e4 > nd2) ? e4 : nd2;
    k_initcnt<<<(mx + 255) / 256, 256>>>(x, temp, dst, hidden, nd2, E);
    int nb = (N + SCAN_BLK - 1) / SCAN_BLK;
    k_scan1<<<nb, SCAN_BLK>>>(N, nb);
    k_fill<<<(e4 + 255) / 256, 256>>>(src, dst, w, E);

    int spmm_blocks = (N + 7) / 8;            // 8 warps (nodes) per 256-thread block
    int gemm_blocks = (N + 63) / 64;
    for (int i = 0; i < L; i++) {
        if (i == 0) k_spmm<1><<<spmm_blocks, 256>>>(N);
        else        k_spmm<0><<<spmm_blocks, 256>>>(N);
        k_gemm<<<gemm_blocks, 256>>>(W + i * D * D, b + i * D, temp, i, hidden, N);
    }
}